// round 13
// baseline (speedup 1.0000x reference)
#include <cuda_runtime.h>
#include <cuda_bf16.h>
#include <stdint.h>

#define NTOK    16384
#define DIM     256
#define NCODES  8192
#define TILES   64
#define MARGIN  5e-4f

// smem layout for k_screen (bytes)
#define SM_A    0               // 128 x 256 bf16 = 64KB (x rows, resident)
#define SM_B0   65536           // code tile buf 0, 64KB
#define SM_B1   131072          // code tile buf 1, 64KB
#define SM_RED  196608          // 128 ints (per-row best reduce)
#define SM_TOT  197120

// Device-global scratch (device-code references only — GB300 ATS trap:
// passing __device__ symbols as host-side kernel args reads host memory).
__device__ unsigned long long g_key[NTOK];
__device__ float    g_rown[NTOK];
__device__ float    g_coden[NCODES];
__device__ double   g_partial[1024];
__device__ uint4    g_xbf[NTOK * 32];     // bf16 x  [row][256]
__device__ uint4    g_cbf[NCODES * 32];   // bf16 cb [code][256]
__device__ unsigned g_cand[NTOK * 16];
__device__ int      g_flagv[NTOK];

// ---------------------------------------------------------------------------
__device__ __forceinline__ uint32_t smem_u32(const void* p) {
    uint32_t a;
    asm("{ .reg .u64 t; cvta.to.shared.u64 t, %1; cvt.u32.u64 %0, t; }" : "=r"(a) : "l"(p));
    return a;
}
__device__ __forceinline__ void ldsm4(uint32_t* r, uint32_t addr) {
    asm volatile("ldmatrix.sync.aligned.m8n8.x4.shared.b16 {%0,%1,%2,%3}, [%4];"
                 : "=r"(r[0]), "=r"(r[1]), "=r"(r[2]), "=r"(r[3]) : "r"(addr));
}
__device__ __forceinline__ void mma16816(float* c, const uint32_t* a,
                                         uint32_t b0, uint32_t b1) {
    asm volatile("mma.sync.aligned.m16n8k16.row.col.f32.bf16.bf16.f32 "
                 "{%0,%1,%2,%3}, {%4,%5,%6,%7}, {%8,%9}, {%0,%1,%2,%3};"
                 : "+f"(c[0]), "+f"(c[1]), "+f"(c[2]), "+f"(c[3])
                 : "r"(a[0]), "r"(a[1]), "r"(a[2]), "r"(a[3]), "r"(b0), "r"(b1));
}
#define CPA(dst, src) \
    asm volatile("cp.async.cg.shared.global [%0], [%1], 16;" :: "r"(dst), "l"(src))
#define CPA_COMMIT() asm volatile("cp.async.commit_group;" ::: "memory")
#define CPA_WAIT0()  asm volatile("cp.async.wait_group 0;" ::: "memory")

// XOR swizzle: granule g (16B units, 0..31) within row r.
__device__ __forceinline__ uint32_t swz(uint32_t g, uint32_t r) {
    return (g & 24u) | ((g ^ r) & 7u);
}

// ---------------------------------------------------------------------------
__global__ void k_prep(const float* __restrict__ x, const float* __restrict__ cb) {
    int id = blockIdx.x * 256 + threadIdx.x;
    const int NX = NTOK * 32, NC = NCODES * 32;
    if (id >= NX + NC) return;
    const float4* s = reinterpret_cast<const float4*>(id < NX ? x : cb) +
                      (size_t)(id < NX ? id : id - NX) * 2;
    float4 a = s[0], b = s[1];
    uint4 o;
    o.x = (uint32_t)__bfloat16_as_ushort(__float2bfloat16(a.x)) |
          ((uint32_t)__bfloat16_as_ushort(__float2bfloat16(a.y)) << 16);
    o.y = (uint32_t)__bfloat16_as_ushort(__float2bfloat16(a.z)) |
          ((uint32_t)__bfloat16_as_ushort(__float2bfloat16(a.w)) << 16);
    o.z = (uint32_t)__bfloat16_as_ushort(__float2bfloat16(b.x)) |
          ((uint32_t)__bfloat16_as_ushort(__float2bfloat16(b.y)) << 16);
    o.w = (uint32_t)__bfloat16_as_ushort(__float2bfloat16(b.z)) |
          ((uint32_t)__bfloat16_as_ushort(__float2bfloat16(b.w)) << 16);
    if (id < NX) g_xbf[id] = o; else g_cbf[id - NX] = o;
}

__global__ void k_zero(void) {
    int n = blockIdx.x * 256 + threadIdx.x;
    if (n < NTOK) g_flagv[n] = 0;
}

__global__ void k_norm(const float* __restrict__ src, int nrows, int which) {
    int gwarp = (blockIdx.x * blockDim.x + threadIdx.x) >> 5;
    int lane  = threadIdx.x & 31;
    if (gwarp >= nrows) return;
    const float4* s4 = reinterpret_cast<const float4*>(src) + (size_t)gwarp * 64;
    float a = 0.0f;
#pragma unroll
    for (int it = 0; it < 2; it++) {
        float4 v = s4[it * 32 + lane];
        a = __fadd_rn(a, __fmul_rn(v.x, v.x));
        a = __fadd_rn(a, __fmul_rn(v.y, v.y));
        a = __fadd_rn(a, __fmul_rn(v.z, v.z));
        a = __fadd_rn(a, __fmul_rn(v.w, v.w));
    }
#pragma unroll
    for (int off = 16; off >= 1; off >>= 1)
        a += __shfl_xor_sync(0xffffffffu, a, off);
    if (lane == 0) { if (which == 0) g_rown[gwarp] = a; else g_coden[gwarp] = a; }
}

// ---------------------------------------------------------------------------
// Screen: bf16 mma.sync GEMM, top-2 per (row, mod-8 code-class) candidates.
__global__ void __launch_bounds__(256, 1) k_screen() {
    extern __shared__ char sm[];
    const uint32_t smb = smem_u32(sm);
    const int tid = threadIdx.x, lane = tid & 31, wid = tid >> 5;
    const int wrow = wid >> 1, wcol = wid & 1;
    const int rowbase = blockIdx.x * 128;
    const uint32_t lsub = lane & 7, lg = lane >> 3;

    // resident A (x rows) + first B tile via cp.async
#pragma unroll
    for (int it = 0; it < 16; it++) {
        int idx = it * 256 + tid;
        uint32_t r = idx >> 5, g = idx & 31;
        uint32_t off = r * 512 + swz(g, r) * 16;
        CPA(smb + SM_A + off,  &g_xbf[(size_t)(rowbase + r) * 32 + g]);
        CPA(smb + SM_B0 + off, &g_cbf[(size_t)r * 32 + g]);
    }
    CPA_COMMIT();

    // per-thread fragment geometry
    const uint32_t arow = wrow * 32 + lsub + ((lg & 1) << 3);   // + i*16
    const uint32_t brow = wcol * 64 + lsub + ((lg >> 1) << 3);  // + j16*16
    const uint32_t gAh = lg >> 1, gBh = lg & 1;

    float rr[4];
#pragma unroll
    for (int sl = 0; sl < 4; sl++)
        rr[sl] = g_rown[rowbase + wrow * 32 + (sl >> 1) * 16 + (lane >> 2) + (sl & 1) * 8];

    float    tv0[4], tv1[4];
    unsigned ti0[4], ti1[4];
#pragma unroll
    for (int sl = 0; sl < 4; sl++) { tv0[sl] = tv1[sl] = 3.4e38f; ti0[sl] = ti1[sl] = 0; }

    CPA_WAIT0();
    __syncthreads();

    for (int t = 0; t < TILES; t++) {
        if (t + 1 < TILES) {      // prefetch next B tile into the other buffer
            uint32_t bdst = smb + ((t + 1) & 1 ? SM_B1 : SM_B0);
#pragma unroll
            for (int it = 0; it < 16; it++) {
                int idx = it * 256 + tid;
                uint32_t r = idx >> 5, g = idx & 31;
                CPA(bdst + r * 512 + swz(g, r) * 16,
                    &g_cbf[(size_t)((t + 1) * 128 + r) * 32 + g]);
            }
            CPA_COMMIT();
        }
        const uint32_t smB = smb + ((t & 1) ? SM_B1 : SM_B0);

        float C[2][8][4];
#pragma unroll
        for (int i = 0; i < 2; i++)
#pragma unroll
            for (int jn = 0; jn < 8; jn++)
#pragma unroll
                for (int c = 0; c < 4; c++) C[i][jn][c] = 0.0f;

#pragma unroll
        for (int s = 0; s < 16; s++) {
            uint32_t A0[4], A1[4];
            uint32_t gA = 2 * s + gAh;
            ldsm4(A0, smb + SM_A + arow * 512 + swz(gA, arow) * 16);
            ldsm4(A1, smb + SM_A + (arow + 16) * 512 + swz(gA, arow + 16) * 16);
            uint32_t gB = 2 * s + gBh;
#pragma unroll
            for (int j16 = 0; j16 < 4; j16++) {
                uint32_t B4[4];
                uint32_t br = brow + j16 * 16;
                ldsm4(B4, smB + br * 512 + swz(gB, br) * 16);
                mma16816(C[0][j16 * 2],     A0, B4[0], B4[1]);
                mma16816(C[0][j16 * 2 + 1], A0, B4[2], B4[3]);
                mma16816(C[1][j16 * 2],     A1, B4[0], B4[1]);
                mma16816(C[1][j16 * 2 + 1], A1, B4[2], B4[3]);
            }
        }

        // epilogue: dist + top-2 per row-slot
#pragma unroll
        for (int jn = 0; jn < 8; jn++) {
            unsigned n0 = (unsigned)(t * 128 + wcol * 64 + jn * 8 + (lane & 3) * 2);
            float cn0 = __ldg(&g_coden[n0]), cn1 = __ldg(&g_coden[n0 + 1]);
#pragma unroll
            for (int i = 0; i < 2; i++) {
#pragma unroll
                for (int rh = 0; rh < 2; rh++) {
                    int sl = i * 2 + rh;
                    float d0 = __fsub_rn(__fadd_rn(rr[sl], cn0), 2.0f * C[i][jn][rh * 2]);
                    float d1 = __fsub_rn(__fadd_rn(rr[sl], cn1), 2.0f * C[i][jn][rh * 2 + 1]);
                    if (d0 < tv1[sl]) {
                        if (d0 < tv0[sl]) { tv1[sl] = tv0[sl]; ti1[sl] = ti0[sl];
                                            tv0[sl] = d0; ti0[sl] = n0; }
                        else              { tv1[sl] = d0; ti1[sl] = n0; }
                    }
                    if (d1 < tv1[sl]) {
                        if (d1 < tv0[sl]) { tv1[sl] = tv0[sl]; ti1[sl] = ti0[sl];
                                            tv0[sl] = d1; ti0[sl] = n0 + 1; }
                        else              { tv1[sl] = d1; ti1[sl] = n0 + 1; }
                    }
                }
            }
        }
        CPA_WAIT0();
        __syncthreads();
    }

    // per-row global best (cross-warp via smem), then flags + candidates
    int* red = reinterpret_cast<int*>(sm + SM_RED);
    if (tid < 128) red[tid] = 0x7f7fffff;
    __syncthreads();
#pragma unroll
    for (int sl = 0; sl < 4; sl++) {
        int lr = wrow * 32 + (sl >> 1) * 16 + (lane >> 2) + (sl & 1) * 8;
        atomicMin(&red[lr], __float_as_int(tv0[sl]));
    }
    __syncthreads();
#pragma unroll
    for (int sl = 0; sl < 4; sl++) {
        int lr = wrow * 32 + (sl >> 1) * 16 + (lane >> 2) + (sl & 1) * 8;
        float gbest = __int_as_float(red[lr]);
        int row = rowbase + lr;
        if (tv1[sl] < gbest + MARGIN)
            atomicOr(&g_flagv[row], 1 << (wcol * 4 + (lane & 3)));
        int base = row * 16 + wcol * 8 + (lane & 3) * 2;
        g_cand[base]     = ti0[sl];
        g_cand[base + 1] = ti1[sl];
    }
}

// ---------------------------------------------------------------------------
// Exact rescore: ascending-d single-accumulator fp32 chain (matches R10/R11),
// dist = fsub(fadd(r,c), 2t), key = (bits<<32)|k → first-index tie-break.
__global__ void k_rescore(const float* __restrict__ x, const float* __restrict__ cb) {
    __shared__ float xs[8][260];
    const int wid  = threadIdx.x >> 5, lane = threadIdx.x & 31;
    const int row  = blockIdx.x * 8 + wid;
    const float rr = g_rown[row];
    const float* xr = x + (size_t)row * DIM;
    for (int d = lane; d < DIM; d += 32) xs[wid][d] = xr[d];
    __syncwarp();
    const float* xsr = xs[wid];

    unsigned long long key = ~0ull;
    if (lane < 16) {
        unsigned k = g_cand[row * 16 + lane];
        const float* er = cb + (size_t)k * DIM;
        float t = 0.0f;
        for (int d = 0; d < DIM; d++) t = __fmaf_rn(xsr[d], er[d], t);
        float dist = __fsub_rn(__fadd_rn(rr, g_coden[k]), 2.0f * t);
        key = ((unsigned long long)__float_as_uint(dist) << 32) | k;
    }
    int fl = g_flagv[row];
    while (fl) {                       // rare per-class exact fallback
        int b = __ffs(fl) - 1; fl &= fl - 1;
        int wc = b >> 2, l = b & 3;
        for (int m = 0; m < 32; m++) {
            int c = m * 32 + lane;     // 0..1023 within class
            int rem = c & 15;
            unsigned n = (unsigned)((c >> 4) * 128 + wc * 64 + (rem >> 1) * 8 + l * 2 + (rem & 1));
            const float* er = cb + (size_t)n * DIM;
            float t = 0.0f;
            for (int d = 0; d < DIM; d++) t = __fmaf_rn(xsr[d], er[d], t);
            float dist = __fsub_rn(__fadd_rn(rr, g_coden[n]), 2.0f * t);
            unsigned long long q = ((unsigned long long)__float_as_uint(dist) << 32) | n;
            if (q < key) key = q;
        }
    }
#pragma unroll
    for (int off = 16; off >= 1; off >>= 1) {
        unsigned long long o = __shfl_xor_sync(0xffffffffu, key, off);
        if (o < key) key = o;
    }
    if (lane == 0) g_key[row] = key;
}

// ---------------------------------------------------------------------------
__global__ void k_gather(const float* __restrict__ x, const float* __restrict__ cb,
                         float* __restrict__ out, int out_size) {
    double ls = 0.0;
    const int total = NTOK * DIM;
    for (int e = blockIdx.x * 256 + threadIdx.x; e < total; e += 1024 * 256) {
        int n = e >> 8, d = e & 255;
        int idx = (int)(unsigned)(g_key[n] & 0xffffffffull);
        float q  = __ldg(&cb[idx * DIM + d]);
        float xv = x[e];
        float diff = __fsub_rn(q, xv);
        if (e < out_size) out[e] = __fadd_rn(xv, diff);
        ls += (double)__fmul_rn(diff, diff);
    }
#pragma unroll
    for (int off = 16; off >= 1; off >>= 1)
        ls += __shfl_xor_sync(0xffffffffu, ls, off);
    __shared__ double ws[8];
    if ((threadIdx.x & 31) == 0) ws[threadIdx.x >> 5] = ls;
    __syncthreads();
    if (threadIdx.x == 0) {
        double t = 0.0;
        for (int w = 0; w < 8; w++) t += ws[w];
        g_partial[blockIdx.x] = t;
    }
}

__global__ void k_finalize(float* __restrict__ out, int out_size) {
    if (blockIdx.x < 64) {
        int n = blockIdx.x * 256 + threadIdx.x;
        int pos = NTOK * DIM + n;
        if (pos < out_size)
            out[pos] = (float)(unsigned)(g_key[n] & 0xffffffffull);
    } else if (threadIdx.x == 0) {
        double s = 0.0;
        for (int b = 0; b < 1024; b++) s += g_partial[b];
        int pos = NTOK * DIM + NTOK;
        if (pos < out_size)
            out[pos] = 0.25f * (float)(s / (double)(NTOK * DIM));
    }
}

// ---------------------------------------------------------------------------
extern "C" void kernel_launch(void* const* d_in, const int* in_sizes, int n_in,
                              void* d_out, int out_size) {
    const float* x  = (const float*)d_in[0];
    const float* cb = (const float*)d_in[1];
    if (n_in >= 2 && in_sizes[0] == NCODES * DIM) {
        cb = (const float*)d_in[0];
        x  = (const float*)d_in[1];
    }
    float* out = (float*)d_out;

    cudaFuncSetAttribute(k_screen, cudaFuncAttributeMaxDynamicSharedMemorySize, SM_TOT);

    k_prep<<<(NTOK * 32 + NCODES * 32 + 255) / 256, 256>>>(x, cb);
    k_zero<<<(NTOK + 255) / 256, 256>>>();
    k_norm<<<NTOK / 8, 256>>>(x, NTOK, 0);
    k_norm<<<NCODES / 8, 256>>>(cb, NCODES, 1);
    k_screen<<<NTOK / 128, 256, SM_TOT>>>();
    k_rescore<<<NTOK / 8, 256>>>(x, cb);
    k_gather<<<1024, 256>>>(x, cb, out, out_size);
    k_finalize<<<65, 256>>>(out, out_size);
}

// round 14
// speedup vs baseline: 5.1973x; 5.1973x over previous
#include <cuda_runtime.h>
#include <cuda_bf16.h>
#include <stdint.h>

#define NTOK   16384
#define DIM    256
#define NCODES 8192

// Device-global scratch (device-code references ONLY — GB300 ATS trap:
// passing __device__ symbols as host-side kernel args reads host memory).
__device__ unsigned long long g_key[NTOK];
__device__ float  g_rown[NTOK];
__device__ float  g_coden[NCODES];
__device__ double g_partial[1024];
__device__ float  g_xT[DIM * NTOK];     // x transposed  [d][token]
__device__ float  g_cT[DIM * NCODES];   // cb transposed [d][code]

// ---------------------------------------------------------------------------
__device__ __forceinline__ uint32_t smem_u32(const void* p) {
    uint32_t a;
    asm("{ .reg .u64 t; cvta.to.shared.u64 t, %1; cvt.u32.u64 %0, t; }" : "=r"(a) : "l"(p));
    return a;
}
__device__ __forceinline__ unsigned long long packf2(float lo, float hi) {
    unsigned long long r;
    asm("mov.b64 %0, {%1, %2};" : "=l"(r) : "f"(lo), "f"(hi));
    return r;
}
__device__ __forceinline__ void unpackf2(unsigned long long v, float& lo, float& hi) {
    asm("mov.b64 {%0, %1}, %2;" : "=f"(lo), "=f"(hi) : "l"(v));
}
// Packed dual fp32 FMA: c.lo += a.lo*b.lo; c.hi += a.hi*b.hi (each IEEE fp32).
__device__ __forceinline__ void fma2(unsigned long long& c, unsigned long long a,
                                     unsigned long long b) {
    asm("fma.rn.f32x2 %0, %1, %2, %0;" : "+l"(c) : "l"(a), "l"(b));
}
#define CPA(dst, src) \
    asm volatile("cp.async.cg.shared.global [%0], [%1], 16;" :: "r"(dst), "l"(src))
#define CPA_COMMIT() asm volatile("cp.async.commit_group;" ::: "memory")
#define CPA_WAIT0()  asm volatile("cp.async.wait_group 0;" ::: "memory")

// ---------------------------------------------------------------------------
// 32x32 tiled transpose into g_xT / g_cT.
__global__ void k_tr(const float* __restrict__ src, int which) {
    __shared__ float t[32][33];
    const int tx = threadIdx.x & 31, ty = threadIdx.x >> 5;     // 256 thr
    const int bx = blockIdx.x * 32;   // row (token/code) base
    const int by = blockIdx.y * 32;   // d base
#pragma unroll
    for (int i = ty; i < 32; i += 8)
        t[i][tx] = src[(size_t)(bx + i) * DIM + by + tx];
    __syncthreads();
    float* dst = which ? g_cT : g_xT;
    const int W = which ? NCODES : NTOK;
#pragma unroll
    for (int i = ty; i < 32; i += 8)
        dst[(size_t)(by + i) * W + bx + tx] = t[tx][i];
}

__global__ void k_init(void) {
    int n = blockIdx.x * 256 + threadIdx.x;
    if (n < NTOK) g_key[n] = ~0ull;
}

__global__ void k_norm(const float* __restrict__ src, int nrows, int which) {
    int gwarp = (blockIdx.x * blockDim.x + threadIdx.x) >> 5;
    int lane  = threadIdx.x & 31;
    if (gwarp >= nrows) return;
    const float4* s4 = reinterpret_cast<const float4*>(src) + (size_t)gwarp * 64;
    float a = 0.0f;
#pragma unroll
    for (int it = 0; it < 2; it++) {
        float4 v = s4[it * 32 + lane];
        a = __fadd_rn(a, __fmul_rn(v.x, v.x));
        a = __fadd_rn(a, __fmul_rn(v.y, v.y));
        a = __fadd_rn(a, __fmul_rn(v.z, v.z));
        a = __fadd_rn(a, __fmul_rn(v.w, v.w));
    }
#pragma unroll
    for (int off = 16; off >= 1; off >>= 1)
        a += __shfl_xor_sync(0xffffffffu, a, off);
    if (lane == 0) { if (which == 0) g_rown[gwarp] = a; else g_coden[gwarp] = a; }
}

// ---------------------------------------------------------------------------
// Fused exact-fp32 GEMM + argmin with packed FFMA2.
// CTA = 128 rows x 128 codes; thread = 4 row-pairs x 4 code-pairs (8x8).
// Each output dot is one ascending-d fp32 FMA chain in a single f32x2 lane —
// bit-identical to the scalar-FFMA kernel. dist = fsub(fadd(r,c), 2t);
// key = (dist_bits<<32)|k gives jnp.argmin's first-index tie-break.
__global__ void __launch_bounds__(256) k_main() {
    extern __shared__ float sm[];    // [xs0|xs1|es0|es1], 4096 floats each (64KB)
    const int tid = threadIdx.x;
    const int tx  = tid & 15;        // code-pair selector
    const int ty  = tid >> 4;        // row-pair selector
    const int rowbase = blockIdx.x * 128;
    const int kbase   = blockIdx.y * 128;
    const uint32_t smb = smem_u32(sm);

    unsigned long long cd[4][4], ca[4][4];
#pragma unroll
    for (int P = 0; P < 4; P++)
#pragma unroll
        for (int Q = 0; Q < 4; Q++) { cd[P][Q] = 0ull; ca[P][Q] = 0ull; }

    // chunk fill via cp.async: 32 d x 128 floats per matrix per chunk
    const int dl = tid >> 3;         // 0..31: d within chunk
    const int gl = tid & 7;          // will cover granules gl, gl+8, gl+16, gl+24
#define FILL(ct, b)                                                              \
    do {                                                                         \
        const float* xsrc = &g_xT[(size_t)((ct) * 32 + dl) * NTOK   + rowbase];  \
        const float* esrc = &g_cT[(size_t)((ct) * 32 + dl) * NCODES + kbase];    \
        uint32_t xd = smb + ((b) * 4096 + dl * 128) * 4;                         \
        uint32_t ed = smb + (8192 + (b) * 4096 + dl * 128) * 4;                  \
        _Pragma("unroll")                                                        \
        for (int it = 0; it < 4; it++) {                                         \
            int g = gl + it * 8;                                                 \
            CPA(xd + g * 16, xsrc + g * 4);                                      \
            CPA(ed + g * 16, esrc + g * 4);                                      \
        }                                                                        \
    } while (0)

    FILL(0, 0);
    CPA_COMMIT();
    CPA_WAIT0();
    __syncthreads();

#pragma unroll 1
    for (int ct = 0; ct < 8; ct++) {
        if (ct < 7) { FILL(ct + 1, (ct + 1) & 1); CPA_COMMIT(); }
        const float* xs = sm + (ct & 1) * 4096;
        const float* es = sm + 8192 + (ct & 1) * 4096;
#pragma unroll 4
        for (int d = 0; d < 32; d++) {
            unsigned long long xa[4], eb[4], es2[4];
#pragma unroll
            for (int P = 0; P < 4; P++) {
                float2 v = *reinterpret_cast<const float2*>(&xs[d * 128 + (ty + 16 * P) * 2]);
                xa[P] = packf2(v.x, v.y);
            }
#pragma unroll
            for (int Q = 0; Q < 4; Q++) {
                float2 e = *reinterpret_cast<const float2*>(&es[d * 128 + (tx + 16 * Q) * 2]);
                eb[Q]  = packf2(e.x, e.y);
                es2[Q] = packf2(e.y, e.x);
            }
#pragma unroll
            for (int P = 0; P < 4; P++)
#pragma unroll
                for (int Q = 0; Q < 4; Q++) {
                    fma2(cd[P][Q], xa[P], eb[Q]);    // (2p,2q) , (2p+1,2q+1)
                    fma2(ca[P][Q], xa[P], es2[Q]);   // (2p,2q+1), (2p+1,2q)
                }
        }
        if (ct < 7) { CPA_WAIT0(); __syncthreads(); }
    }

    // Epilogue: distances + lexicographic argmin.
    float rr[8];
#pragma unroll
    for (int P = 0; P < 4; P++) {
        rr[P * 2]     = g_rown[rowbase + 2 * (ty + 16 * P)];
        rr[P * 2 + 1] = g_rown[rowbase + 2 * (ty + 16 * P) + 1];
    }
    unsigned long long bk[8];
#pragma unroll
    for (int i = 0; i < 8; i++) bk[i] = ~0ull;

#pragma unroll
    for (int Q = 0; Q < 4; Q++) {
        int k0 = kbase + 2 * (tx + 16 * Q);
        float cn0 = g_coden[k0], cn1 = g_coden[k0 + 1];
#pragma unroll
        for (int P = 0; P < 4; P++) {
            float dlo, dhi, alo, ahi;
            unpackf2(cd[P][Q], dlo, dhi);
            unpackf2(ca[P][Q], alo, ahi);
            // (row 2p, code 2q)=dlo  (2p,2q+1)=alo  (2p+1,2q)=ahi  (2p+1,2q+1)=dhi
            float d00 = __fsub_rn(__fadd_rn(rr[P * 2],     cn0), 2.0f * dlo);
            float d01 = __fsub_rn(__fadd_rn(rr[P * 2],     cn1), 2.0f * alo);
            float d10 = __fsub_rn(__fadd_rn(rr[P * 2 + 1], cn0), 2.0f * ahi);
            float d11 = __fsub_rn(__fadd_rn(rr[P * 2 + 1], cn1), 2.0f * dhi);
            unsigned long long q;
            q = ((unsigned long long)__float_as_uint(d00) << 32) | (unsigned)k0;
            if (q < bk[P * 2]) bk[P * 2] = q;
            q = ((unsigned long long)__float_as_uint(d01) << 32) | (unsigned)(k0 + 1);
            if (q < bk[P * 2]) bk[P * 2] = q;
            q = ((unsigned long long)__float_as_uint(d10) << 32) | (unsigned)k0;
            if (q < bk[P * 2 + 1]) bk[P * 2 + 1] = q;
            q = ((unsigned long long)__float_as_uint(d11) << 32) | (unsigned)(k0 + 1);
            if (q < bk[P * 2 + 1]) bk[P * 2 + 1] = q;
        }
    }
    // reduce across the 16 tx lanes sharing this ty (lane = (ty&1)*16+tx)
#pragma unroll
    for (int i = 0; i < 8; i++) {
        unsigned long long k = bk[i];
#pragma unroll
        for (int off = 8; off >= 1; off >>= 1) {
            unsigned long long o = __shfl_xor_sync(0xffffffffu, k, off);
            if (o < k) k = o;
        }
        if (tx == 0)
            atomicMin(&g_key[rowbase + 2 * (ty + 16 * (i >> 1)) + (i & 1)], k);
    }
}

// ---------------------------------------------------------------------------
__global__ void k_gather(const float* __restrict__ x, const float* __restrict__ cb,
                         float* __restrict__ out, int out_size) {
    double ls = 0.0;
    const int total = NTOK * DIM;
    for (int e = blockIdx.x * 256 + threadIdx.x; e < total; e += 1024 * 256) {
        int n = e >> 8, d = e & 255;
        int idx = (int)(unsigned)(g_key[n] & 0xffffffffull);
        float q  = __ldg(&cb[idx * DIM + d]);
        float xv = x[e];
        float diff = __fsub_rn(q, xv);
        if (e < out_size) out[e] = __fadd_rn(xv, diff);
        ls += (double)__fmul_rn(diff, diff);
    }
#pragma unroll
    for (int off = 16; off >= 1; off >>= 1)
        ls += __shfl_xor_sync(0xffffffffu, ls, off);
    __shared__ double ws[8];
    if ((threadIdx.x & 31) == 0) ws[threadIdx.x >> 5] = ls;
    __syncthreads();
    if (threadIdx.x == 0) {
        double t = 0.0;
        for (int w = 0; w < 8; w++) t += ws[w];
        g_partial[blockIdx.x] = t;
    }
}

__global__ void k_finalize(float* __restrict__ out, int out_size) {
    if (blockIdx.x < 64) {
        int n = blockIdx.x * 256 + threadIdx.x;
        int pos = NTOK * DIM + n;
        if (pos < out_size)
            out[pos] = (float)(unsigned)(g_key[n] & 0xffffffffull);
    } else if (threadIdx.x == 0) {
        double s = 0.0;
        for (int b = 0; b < 1024; b++) s += g_partial[b];
        int pos = NTOK * DIM + NTOK;
        if (pos < out_size)
            out[pos] = 0.25f * (float)(s / (double)(NTOK * DIM));
    }
}

// ---------------------------------------------------------------------------
extern "C" void kernel_launch(void* const* d_in, const int* in_sizes, int n_in,
                              void* d_out, int out_size) {
    const float* x  = (const float*)d_in[0];
    const float* cb = (const float*)d_in[1];
    if (n_in >= 2 && in_sizes[0] == NCODES * DIM) {
        cb = (const float*)d_in[0];
        x  = (const float*)d_in[1];
    }
    float* out = (float*)d_out;

    cudaFuncSetAttribute(k_main, cudaFuncAttributeMaxDynamicSharedMemorySize, 65536);

    k_tr<<<dim3(NTOK / 32, DIM / 32), 256>>>(x, 0);
    k_tr<<<dim3(NCODES / 32, DIM / 32), 256>>>(cb, 1);
    k_init<<<(NTOK + 255) / 256, 256>>>();
    k_norm<<<NTOK / 8, 256>>>(x, NTOK, 0);
    k_norm<<<NCODES / 8, 256>>>(cb, NCODES, 1);
    k_main<<<dim3(NTOK / 128, NCODES / 128), 256, 65536>>>();
    k_gather<<<1024, 256>>>(x, cb, out, out_size);
    k_finalize<<<65, 256>>>(out, out_size);
}